// round 16
// baseline (speedup 1.0000x reference)
#include <cuda_runtime.h>
#include <cuda_bf16.h>
#include <math.h>
#include <stdint.h>

// ---------------- problem constants ----------------
#define BATCH 8
#define NSEQ  4096
#define FDIM  1024
#define LDIM  256
#define ODIM  1024
#define TFW   (2 * LDIM)    // 512: theta|phi packed width

// ---------------- scratch (device globals) ----------------
__device__ __nv_bfloat16 g_xh [BATCH * NSEQ * FDIM];
__device__ __nv_bfloat16 g_xl [BATCH * NSEQ * FDIM];
__device__ __nv_bfloat16 g_TFh[BATCH * NSEQ * TFW];    // [theta | phi]
__device__ __nv_bfloat16 g_TFl[BATCH * NSEQ * TFW];
__device__ __nv_bfloat16 g_Ph [BATCH * LDIM * FDIM];   // P = scale * phi^T x
__device__ __nv_bfloat16 g_Pl [BATCH * LDIM * FDIM];
__device__ __nv_bfloat16 g_Qh [BATCH * ODIM * LDIM];   // QT
__device__ __nv_bfloat16 g_Ql [BATCH * ODIM * LDIM];
__device__ __nv_bfloat16 g_Wch[TFW * FDIM];            // [Wtheta ; Wphi]
__device__ __nv_bfloat16 g_Wcl[TFW * FDIM];
__device__ __nv_bfloat16 g_Wgh[ODIM * FDIM];
__device__ __nv_bfloat16 g_Wgl[ODIM * FDIM];

// ---------------- PTX helpers ----------------
__device__ __forceinline__ uint32_t smem_u32(const void* p) {
    uint32_t a;
    asm("{ .reg .u64 t; cvta.to.shared.u64 t, %1; cvt.u32.u64 %0, t; }" : "=r"(a) : "l"(p));
    return a;
}
__device__ __forceinline__ void cp16(uint32_t dst, const void* src) {
    asm volatile("cp.async.cg.shared.global [%0], [%1], 16;\n" :: "r"(dst), "l"(src));
}
#define CP_COMMIT()  asm volatile("cp.async.commit_group;\n" ::: "memory")
#define CP_WAIT0()   asm volatile("cp.async.wait_group 0;\n" ::: "memory")
#define CP_WAIT1()   asm volatile("cp.async.wait_group 1;\n" ::: "memory")
#define CP_WAIT2()   asm volatile("cp.async.wait_group 2;\n" ::: "memory")

__device__ __forceinline__ void ldsm4(uint32_t* r, uint32_t addr) {
    asm volatile("ldmatrix.sync.aligned.m8n8.x4.shared.b16 {%0,%1,%2,%3}, [%4];"
        : "=r"(r[0]), "=r"(r[1]), "=r"(r[2]), "=r"(r[3]) : "r"(addr));
}
__device__ __forceinline__ void ldsm4t(uint32_t* r, uint32_t addr) {
    asm volatile("ldmatrix.sync.aligned.m8n8.x4.trans.shared.b16 {%0,%1,%2,%3}, [%4];"
        : "=r"(r[0]), "=r"(r[1]), "=r"(r[2]), "=r"(r[3]) : "r"(addr));
}
__device__ __forceinline__ void mma16816(float* d, const uint32_t* a, const uint32_t* b) {
    asm volatile(
        "mma.sync.aligned.m16n8k16.row.col.f32.bf16.bf16.f32 "
        "{%0,%1,%2,%3}, {%4,%5,%6,%7}, {%8,%9}, {%0,%1,%2,%3};"
        : "+f"(d[0]), "+f"(d[1]), "+f"(d[2]), "+f"(d[3])
        : "r"(a[0]), "r"(a[1]), "r"(a[2]), "r"(a[3]), "r"(b[0]), "r"(b[1]));
}
__device__ __forceinline__ uint32_t sw128(uint32_t off) {
    return off ^ ((off >> 3) & 0x70);
}
__device__ __forceinline__ void split_bf16(float v, __nv_bfloat16& h, __nv_bfloat16& l) {
    h = __float2bfloat16(v);
    l = __float2bfloat16(v - __bfloat162float(h));
}

// smem: 3 stages x 64KB. Stage: Ah | Al | Bh | Bl (16KB each)
#define STAGE_BYTES 65536
#define OFF_AH 0
#define OFF_AL 16384
#define OFF_BH 32768
#define OFF_BL 49152
#define GEMM_SMEM (3 * STAGE_BYTES)

// ============================================================================
// Generic HMMA GEMM: D[m,n] = alpha * sum_k A[m,k]*B[n,k]  (bf16x3, batched)
// A rows stride ldA, B rows stride ldB (both K-major). mode 0: fp32 out;
// mode 1: bf16 hi/lo out.  (R7 pipeline + ld params; correctness proven R15)
// ============================================================================
__global__ void __launch_bounds__(256, 1)
gemm_bf16x3(const __nv_bfloat16* __restrict__ Ah, const __nv_bfloat16* __restrict__ Al, int ldA,
            const __nv_bfloat16* __restrict__ Bh, const __nv_bfloat16* __restrict__ Bl, int ldB,
            float* __restrict__ Df, __nv_bfloat16* __restrict__ Dh, __nv_bfloat16* __restrict__ Dl,
            int N, int K,
            long long sA, long long sB, long long sD,
            float alpha, int mode)
{
    extern __shared__ char smem[];
    const int b = blockIdx.z;
    Ah += (long long)b * sA;  Al += (long long)b * sA;
    Bh += (long long)b * sB;  Bl += (long long)b * sB;

    const int m0 = blockIdx.y * 128;
    const int n0 = blockIdx.x * 128;
    const int tid = (int)threadIdx.x;
    const int wid = tid >> 5;
    const int lid = tid & 31;
    const int wm = (wid >> 2) * 64;
    const int wn = (wid & 3) * 32;

    const uint32_t sb = smem_u32(smem);
    const int nch = K >> 6;

    auto load_chunk = [&](int kc, int stage) {
        const long long kofs = (long long)kc * 64;
        const uint32_t sbase = sb + stage * STAGE_BYTES;
#pragma unroll
        for (int j = 0; j < 4; j++) {
            int idx = j * 256 + tid;
            int r   = idx >> 3;
            int cb  = (idx & 7) << 4;
            uint32_t sw = sw128((uint32_t)(r * 128 + cb));
            long long ea = (long long)(m0 + r) * ldA + kofs + (cb >> 1);
            long long eb = (long long)(n0 + r) * ldB + kofs + (cb >> 1);
            cp16(sbase + OFF_AH + sw, Ah + ea);
            cp16(sbase + OFF_AL + sw, Al + ea);
            cp16(sbase + OFF_BH + sw, Bh + eb);
            cp16(sbase + OFF_BL + sw, Bl + eb);
        }
        CP_COMMIT();
    };

    float acc[4][4][4];
#pragma unroll
    for (int i = 0; i < 4; i++)
#pragma unroll
        for (int j = 0; j < 4; j++)
#pragma unroll
            for (int c = 0; c < 4; c++) acc[i][j][c] = 0.0f;

    const int a_row = wm + (lid & 15);
    const int a_cb  = (lid >> 4) * 16;
    const int b_row = wn + (lid & 7) + ((lid >> 4) & 1) * 8;
    const int b_cb  = ((lid >> 3) & 1) * 16;

    uint32_t ahf[2][4][4], alf[2][4][4], bhf[2][2][4], blf[2][2][4];

    auto ldfrags = [&](int k16, int buf, uint32_t sbase) {
        const int kb = k16 * 32;
#pragma unroll
        for (int mt = 0; mt < 4; mt++) {
            uint32_t sw = sw128((uint32_t)((a_row + mt * 16) * 128 + kb + a_cb));
            ldsm4(ahf[buf][mt], sbase + OFF_AH + sw);
            ldsm4(alf[buf][mt], sbase + OFF_AL + sw);
        }
#pragma unroll
        for (int np = 0; np < 2; np++) {
            uint32_t sw = sw128((uint32_t)((b_row + np * 16) * 128 + kb + b_cb));
            ldsm4(bhf[buf][np], sbase + OFF_BH + sw);
            ldsm4(blf[buf][np], sbase + OFF_BL + sw);
        }
    };

    load_chunk(0, 0);
    if (nch > 1) load_chunk(1, 1);
    if (nch > 2) load_chunk(2, 2);

    for (int i = 0; i < nch; i++) {
        const int s = i % 3;
        const int rem = nch - 1 - i;
        if (rem >= 2)      { CP_WAIT2(); }
        else if (rem == 1) { CP_WAIT1(); }
        else               { CP_WAIT0(); }
        __syncthreads();

        const uint32_t sbase = sb + s * STAGE_BYTES;
        ldfrags(0, 0, sbase);
        int cur = 0;
#pragma unroll
        for (int k16 = 0; k16 < 4; k16++) {
            if (k16 < 3) ldfrags(k16 + 1, cur ^ 1, sbase);
            if (k16 == 3) {
                __syncthreads();
                if (i + 3 < nch) load_chunk(i + 3, s);
            }
#pragma unroll
            for (int p = 0; p < 3; p++) {
#pragma unroll
                for (int mt = 0; mt < 4; mt++) {
                    const uint32_t* af = (p == 2) ? alf[cur][mt] : ahf[cur][mt];
#pragma unroll
                    for (int nt = 0; nt < 4; nt++) {
                        const uint32_t* bf = (p == 1) ? &blf[cur][nt >> 1][(nt & 1) * 2]
                                                      : &bhf[cur][nt >> 1][(nt & 1) * 2];
                        mma16816(acc[mt][nt], af, bf);
                    }
                }
            }
            cur ^= 1;
        }
    }

    const int er = lid >> 2;
    const int ec = (lid & 3) * 2;
#pragma unroll
    for (int mt = 0; mt < 4; mt++) {
#pragma unroll
        for (int nt = 0; nt < 4; nt++) {
            const long long row0 = m0 + wm + mt * 16 + er;
            const long long col  = n0 + wn + nt * 8 + ec;
            if (mode == 0) {
                float2 v0, v1;
                v0.x = acc[mt][nt][0] * alpha; v0.y = acc[mt][nt][1] * alpha;
                v1.x = acc[mt][nt][2] * alpha; v1.y = acc[mt][nt][3] * alpha;
                *(float2*)(Df + (long long)b * sD + row0 * N + col)       = v0;
                *(float2*)(Df + (long long)b * sD + (row0 + 8) * N + col) = v1;
            } else {
                float p0 = acc[mt][nt][0] * alpha, p1 = acc[mt][nt][1] * alpha;
                float p2 = acc[mt][nt][2] * alpha, p3 = acc[mt][nt][3] * alpha;
                __nv_bfloat16 h0, h1, h2, h3, l0, l1, l2, l3;
                split_bf16(p0, h0, l0); split_bf16(p1, h1, l1);
                split_bf16(p2, h2, l2); split_bf16(p3, h3, l3);
                long long base = (long long)b * sD;
                *(__nv_bfloat162*)(Dh + base + row0 * N + col)       = __nv_bfloat162(h0, h1);
                *(__nv_bfloat162*)(Dh + base + (row0 + 8) * N + col) = __nv_bfloat162(h2, h3);
                *(__nv_bfloat162*)(Dl + base + row0 * N + col)       = __nv_bfloat162(l0, l1);
                *(__nv_bfloat162*)(Dl + base + (row0 + 8) * N + col) = __nv_bfloat162(l2, l3);
            }
        }
    }
}

// ============================================================================
// Trans-trans GEMM: D[m,n] = alpha * sum_k A[k,m]*B[k,n]  (bf16x3, batched)
// A stored [K, ldA] (m contiguous), B stored [K, ldB] (n contiguous).
// ============================================================================
__global__ void __launch_bounds__(256, 1)
gemm_tt_bf16x3(const __nv_bfloat16* __restrict__ Ah, const __nv_bfloat16* __restrict__ Al, int ldA,
               const __nv_bfloat16* __restrict__ Bh, const __nv_bfloat16* __restrict__ Bl, int ldB,
               __nv_bfloat16* __restrict__ Dh, __nv_bfloat16* __restrict__ Dl,
               int N, int K,
               long long sA, long long sB, long long sD,
               float alpha)
{
    extern __shared__ char smem[];
    const int b = blockIdx.z;
    Ah += (long long)b * sA;  Al += (long long)b * sA;
    Bh += (long long)b * sB;  Bl += (long long)b * sB;

    const int m0 = blockIdx.y * 128;
    const int n0 = blockIdx.x * 128;
    const int tid = (int)threadIdx.x;
    const int wid = tid >> 5;
    const int lid = tid & 31;
    const int wm = (wid >> 2) * 64;
    const int wn = (wid & 3) * 32;

    const uint32_t sb = smem_u32(smem);

    auto load_chunk = [&](int kc, int stage) {
        const uint32_t sbase = sb + stage * STAGE_BYTES;
        const long long s0 = (long long)kc * 64;
#pragma unroll
        for (int j = 0; j < 4; j++) {
            int idx = j * 256 + tid;
            int r   = idx >> 4;
            int cb  = (idx & 15) << 4;
            uint32_t sw = (uint32_t)(r * 256 + cb) ^ (uint32_t)((r & 7) << 4);
            cp16(sbase + OFF_AH + sw, Ah + (s0 + r) * ldA + m0 + (cb >> 1));
            cp16(sbase + OFF_AL + sw, Al + (s0 + r) * ldA + m0 + (cb >> 1));
            cp16(sbase + OFF_BH + sw, Bh + (s0 + r) * ldB + n0 + (cb >> 1));
            cp16(sbase + OFF_BL + sw, Bl + (s0 + r) * ldB + n0 + (cb >> 1));
        }
        CP_COMMIT();
    };

    float acc[4][4][4];
#pragma unroll
    for (int i = 0; i < 4; i++)
#pragma unroll
        for (int j = 0; j < 4; j++)
#pragma unroll
            for (int c = 0; c < 4; c++) acc[i][j][c] = 0.0f;

    const int a_krow  = ((lid >> 4) & 1) * 8 + (lid & 7);
    const int a_mbyte = ((lid >> 3) & 1) * 16;
    const int b_krow  = ((lid >> 3) & 1) * 8 + (lid & 7);
    const int b_nbyte = ((lid >> 4) & 1) * 16;

    uint32_t ahf[2][4][4], alf[2][4][4], bhf[2][2][4], blf[2][2][4];

    auto ldfrags = [&](int k16, int buf, uint32_t sbase) {
#pragma unroll
        for (int mt = 0; mt < 4; mt++) {
            uint32_t off = (uint32_t)((k16 * 16 + a_krow) * 256 + (wm + mt * 16) * 2 + a_mbyte);
            off ^= (uint32_t)((a_krow & 7) << 4);
            ldsm4t(ahf[buf][mt], sbase + OFF_AH + off);
            ldsm4t(alf[buf][mt], sbase + OFF_AL + off);
        }
#pragma unroll
        for (int np = 0; np < 2; np++) {
            uint32_t off = (uint32_t)((k16 * 16 + b_krow) * 256 + (wn + np * 16) * 2 + b_nbyte);
            off ^= (uint32_t)((b_krow & 7) << 4);
            ldsm4t(bhf[buf][np], sbase + OFF_BH + off);
            ldsm4t(blf[buf][np], sbase + OFF_BL + off);
        }
    };

    const int nch = K >> 6;
    load_chunk(0, 0);
    if (nch > 1) load_chunk(1, 1);
    if (nch > 2) load_chunk(2, 2);

    for (int i = 0; i < nch; i++) {
        const int s = i % 3;
        const int rem = nch - 1 - i;
        if (rem >= 2)      { CP_WAIT2(); }
        else if (rem == 1) { CP_WAIT1(); }
        else               { CP_WAIT0(); }
        __syncthreads();

        const uint32_t sbase = sb + s * STAGE_BYTES;
        ldfrags(0, 0, sbase);
        int cur = 0;
#pragma unroll
        for (int k16 = 0; k16 < 4; k16++) {
            if (k16 < 3) ldfrags(k16 + 1, cur ^ 1, sbase);
            if (k16 == 3) {
                __syncthreads();
                if (i + 3 < nch) load_chunk(i + 3, s);
            }
#pragma unroll
            for (int p = 0; p < 3; p++) {
#pragma unroll
                for (int mt = 0; mt < 4; mt++) {
                    const uint32_t* af = (p == 2) ? alf[cur][mt] : ahf[cur][mt];
#pragma unroll
                    for (int nt = 0; nt < 4; nt++) {
                        const uint32_t* bf = (p == 1) ? &blf[cur][nt >> 1][(nt & 1) * 2]
                                                      : &bhf[cur][nt >> 1][(nt & 1) * 2];
                        mma16816(acc[mt][nt], af, bf);
                    }
                }
            }
            cur ^= 1;
        }
    }

    const int er = lid >> 2;
    const int ec = (lid & 3) * 2;
    const long long base = (long long)b * sD;
#pragma unroll
    for (int mt = 0; mt < 4; mt++) {
#pragma unroll
        for (int nt = 0; nt < 4; nt++) {
            const long long row0 = m0 + wm + mt * 16 + er;
            const long long col  = n0 + wn + nt * 8 + ec;
            float p0 = acc[mt][nt][0] * alpha, p1 = acc[mt][nt][1] * alpha;
            float p2 = acc[mt][nt][2] * alpha, p3 = acc[mt][nt][3] * alpha;
            __nv_bfloat16 h0, h1, h2, h3, l0, l1, l2, l3;
            split_bf16(p0, h0, l0); split_bf16(p1, h1, l1);
            split_bf16(p2, h2, l2); split_bf16(p3, h3, l3);
            *(__nv_bfloat162*)(Dh + base + row0 * N + col)       = __nv_bfloat162(h0, h1);
            *(__nv_bfloat162*)(Dh + base + (row0 + 8) * N + col) = __nv_bfloat162(h2, h3);
            *(__nv_bfloat162*)(Dl + base + row0 * N + col)       = __nv_bfloat162(l0, l1);
            *(__nv_bfloat162*)(Dl + base + (row0 + 8) * N + col) = __nv_bfloat162(l2, l3);
        }
    }
}

// ---------------- conversion kernels ----------------
__global__ void conv_x_kernel(const float4* __restrict__ x,
                              uint4* __restrict__ xh4, uint4* __restrict__ xl4)
{
    const int i = blockIdx.x * blockDim.x + threadIdx.x;
    float4 a = x[2 * i];
    float4 c = x[2 * i + 1];
    __nv_bfloat16 h[8], l[8];
    split_bf16(a.x, h[0], l[0]); split_bf16(a.y, h[1], l[1]);
    split_bf16(a.z, h[2], l[2]); split_bf16(a.w, h[3], l[3]);
    split_bf16(c.x, h[4], l[4]); split_bf16(c.y, h[5], l[5]);
    split_bf16(c.z, h[6], l[6]); split_bf16(c.w, h[7], l[7]);
    uint4 vh, vl;
    __nv_bfloat162 t0(h[0], h[1]), t1(h[2], h[3]), t2(h[4], h[5]), t3(h[6], h[7]);
    __nv_bfloat162 u0(l[0], l[1]), u1(l[2], l[3]), u2(l[4], l[5]), u3(l[6], l[7]);
    vh.x = *(uint32_t*)&t0; vh.y = *(uint32_t*)&t1; vh.z = *(uint32_t*)&t2; vh.w = *(uint32_t*)&t3;
    vl.x = *(uint32_t*)&u0; vl.y = *(uint32_t*)&u1; vl.z = *(uint32_t*)&u2; vl.w = *(uint32_t*)&u3;
    xh4[i] = vh;
    xl4[i] = vl;
}

__global__ void conv_pair_kernel(const float* __restrict__ in,
                                 __nv_bfloat16* __restrict__ oh, __nv_bfloat16* __restrict__ ol, int n)
{
    int i = blockIdx.x * blockDim.x + threadIdx.x;
    if (i < n) {
        __nv_bfloat16 h, l; split_bf16(in[i], h, l);
        oh[i] = h; ol[i] = l;
    }
}

// ---------------- launcher (R14 skeleton + fused theta|phi) ----------------
extern "C" void kernel_launch(void* const* d_in, const int* in_sizes, int n_in,
                              void* d_out, int out_size)
{
    const float* x  = (const float*)d_in[0];
    const float* Wt = (const float*)d_in[1];
    const float* Wp = (const float*)d_in[2];
    const float* Wg = (const float*)d_in[3];
    float* out = (float*)d_out;

    __nv_bfloat16 *xh, *xl, *TFh, *TFl, *Ph, *Pl, *Qh, *Ql;
    __nv_bfloat16 *Wch, *Wcl, *Wgh, *Wgl;
    cudaGetSymbolAddress((void**)&xh, g_xh);   cudaGetSymbolAddress((void**)&xl, g_xl);
    cudaGetSymbolAddress((void**)&TFh, g_TFh); cudaGetSymbolAddress((void**)&TFl, g_TFl);
    cudaGetSymbolAddress((void**)&Ph, g_Ph);   cudaGetSymbolAddress((void**)&Pl, g_Pl);
    cudaGetSymbolAddress((void**)&Qh, g_Qh);   cudaGetSymbolAddress((void**)&Ql, g_Ql);
    cudaGetSymbolAddress((void**)&Wch, g_Wch); cudaGetSymbolAddress((void**)&Wcl, g_Wcl);
    cudaGetSymbolAddress((void**)&Wgh, g_Wgh); cudaGetSymbolAddress((void**)&Wgl, g_Wgl);

    cudaFuncSetAttribute(gemm_bf16x3,    cudaFuncAttributeMaxDynamicSharedMemorySize, GEMM_SMEM);
    cudaFuncSetAttribute(gemm_tt_bf16x3, cudaFuncAttributeMaxDynamicSharedMemorySize, GEMM_SMEM);

    static cudaStream_t s2 = nullptr;
    static cudaEvent_t evFork = nullptr, evWc = nullptr, evWg = nullptr, evTF1 = nullptr, evD = nullptr;
    if (!s2) {
        cudaStreamCreateWithFlags(&s2, cudaStreamNonBlocking);
        cudaEventCreateWithFlags(&evFork, cudaEventDisableTiming);
        cudaEventCreateWithFlags(&evWc,   cudaEventDisableTiming);
        cudaEventCreateWithFlags(&evWg,   cudaEventDisableTiming);
        cudaEventCreateWithFlags(&evTF1,  cudaEventDisableTiming);
        cudaEventCreateWithFlags(&evD,    cudaEventDisableTiming);
    }

    const float scale = 1.0f / 32.0f;  // 1/sqrt(1024)
    const int HB = BATCH / 2;
    const int nxh = HB * NSEQ * FDIM;

    const long long sX  = (long long)NSEQ * FDIM;
    const long long sTF = (long long)NSEQ * TFW;
    const long long sP  = (long long)LDIM * FDIM;
    const long long sQ  = (long long)ODIM * LDIM;

    cudaEventRecord(evFork, 0);

    // ---- stream 0: conv x batches 0-3 immediately (no weight wait) ----
    conv_x_kernel<<<nxh / 8 / 256, 256>>>((const float4*)x, (uint4*)xh, (uint4*)xl);

    // ---- stream s2: weight convs, conv x batches 4-7, TF[4-7] ----
    cudaStreamWaitEvent(s2, evFork, 0);
    conv_pair_kernel<<<(LDIM * FDIM) / 256, 256, 0, s2>>>(Wt, Wch, Wcl, LDIM * FDIM);
    conv_pair_kernel<<<(LDIM * FDIM) / 256, 256, 0, s2>>>(
        Wp, Wch + (long long)LDIM * FDIM, Wcl + (long long)LDIM * FDIM, LDIM * FDIM);
    cudaEventRecord(evWc, s2);
    conv_pair_kernel<<<(ODIM * FDIM) / 256, 256, 0, s2>>>(Wg, Wgh, Wgl, ODIM * FDIM);
    cudaEventRecord(evWg, s2);
    conv_x_kernel<<<nxh / 8 / 256, 256, 0, s2>>>(
        (const float4*)(x + (long long)HB * sX),
        (uint4*)(xh + (long long)HB * sX), (uint4*)(xl + (long long)HB * sX));
    // TF[4-7] = x[4-7] @ [Wth;Wph]^T : M=4096, N=512, K=1024  (all deps stream-local)
    gemm_bf16x3<<<dim3(TFW / 128, NSEQ / 128, HB), 256, GEMM_SMEM, s2>>>(
        xh + (long long)HB * sX, xl + (long long)HB * sX, FDIM, Wch, Wcl, FDIM, nullptr,
        TFh + (long long)HB * sTF, TFl + (long long)HB * sTF, TFW, FDIM, sX, 0, sTF, 1.0f, 1);
    cudaEventRecord(evTF1, s2);

    // ---- stream 0: TF[0-3] -> P -> QT -> out (full-batch launches) ----
    cudaStreamWaitEvent(0, evWc, 0);
    gemm_bf16x3<<<dim3(TFW / 128, NSEQ / 128, HB), 256, GEMM_SMEM>>>(
        xh, xl, FDIM, Wch, Wcl, FDIM, nullptr,
        TFh, TFl, TFW, FDIM, sX, 0, sTF, 1.0f, 1);

    cudaStreamWaitEvent(0, evTF1, 0);
    // P[l,f] = scale * sum_s phi[s,l] * x[s,f] : M=256, N=1024, K=4096 (tt), all 8
    gemm_tt_bf16x3<<<dim3(FDIM / 128, LDIM / 128, BATCH), 256, GEMM_SMEM>>>(
        TFh + LDIM, TFl + LDIM, TFW, xh, xl, FDIM,
        Ph, Pl, FDIM, NSEQ, sTF, sX, sP, scale);

    cudaStreamWaitEvent(0, evWg, 0);
    // QT[o,l] = sum_f Wg[o,f] * P[l,f] : M=1024, N=256, K=1024, all 8
    gemm_bf16x3<<<dim3(LDIM / 128, ODIM / 128, BATCH), 256, GEMM_SMEM>>>(
        Wgh, Wgl, FDIM, Ph, Pl, FDIM, nullptr,
        Qh, Ql, LDIM, FDIM, 0, sP, sQ, 1.0f, 1);

    // out[s,o] = sum_l theta[s,l] * QT[o,l] : M=4096, N=1024, K=256, all 8
    gemm_bf16x3<<<dim3(ODIM / 128, NSEQ / 128, BATCH), 256, GEMM_SMEM>>>(
        TFh, TFl, TFW, Qh, Ql, LDIM,
        out, nullptr, nullptr, ODIM, LDIM, sTF, sQ, sX, 1.0f, 0);

    cudaEventRecord(evD, s2);
    cudaStreamWaitEvent(0, evD, 0);
}

// round 17
// speedup vs baseline: 1.0438x; 1.0438x over previous
#include <cuda_runtime.h>
#include <cuda_bf16.h>
#include <math.h>
#include <stdint.h>

// ---------------- problem constants ----------------
#define BATCH 8
#define NSEQ  4096
#define FDIM  1024
#define LDIM  256
#define ODIM  1024

// ---------------- scratch (device globals) ----------------
__device__ __nv_bfloat16 g_xh [BATCH * NSEQ * FDIM];
__device__ __nv_bfloat16 g_xl [BATCH * NSEQ * FDIM];
__device__ __nv_bfloat16 g_Th [BATCH * NSEQ * LDIM];   // theta = x Wth^T
__device__ __nv_bfloat16 g_Tl [BATCH * NSEQ * LDIM];
__device__ __nv_bfloat16 g_Fh [BATCH * NSEQ * LDIM];   // phi = x Wph^T
__device__ __nv_bfloat16 g_Fl [BATCH * NSEQ * LDIM];
__device__ __nv_bfloat16 g_Ph [BATCH * LDIM * FDIM];   // P = scale * phi^T x
__device__ __nv_bfloat16 g_Pl [BATCH * LDIM * FDIM];
__device__ __nv_bfloat16 g_Qh [BATCH * ODIM * LDIM];   // QT
__device__ __nv_bfloat16 g_Ql [BATCH * ODIM * LDIM];
__device__ __nv_bfloat16 g_Wth[LDIM * FDIM];
__device__ __nv_bfloat16 g_Wtl[LDIM * FDIM];
__device__ __nv_bfloat16 g_Wph[LDIM * FDIM];
__device__ __nv_bfloat16 g_Wpl[LDIM * FDIM];
__device__ __nv_bfloat16 g_Wgh[ODIM * FDIM];
__device__ __nv_bfloat16 g_Wgl[ODIM * FDIM];

// ---------------- PTX helpers ----------------
__device__ __forceinline__ uint32_t smem_u32(const void* p) {
    uint32_t a;
    asm("{ .reg .u64 t; cvta.to.shared.u64 t, %1; cvt.u32.u64 %0, t; }" : "=r"(a) : "l"(p));
    return a;
}
__device__ __forceinline__ void cp16(uint32_t dst, const void* src) {
    asm volatile("cp.async.cg.shared.global [%0], [%1], 16;\n" :: "r"(dst), "l"(src));
}
#define CP_COMMIT()  asm volatile("cp.async.commit_group;\n" ::: "memory")
#define CP_WAIT0()   asm volatile("cp.async.wait_group 0;\n" ::: "memory")
#define CP_WAIT1()   asm volatile("cp.async.wait_group 1;\n" ::: "memory")
#define CP_WAIT2()   asm volatile("cp.async.wait_group 2;\n" ::: "memory")

__device__ __forceinline__ void ldsm4(uint32_t* r, uint32_t addr) {
    asm volatile("ldmatrix.sync.aligned.m8n8.x4.shared.b16 {%0,%1,%2,%3}, [%4];"
        : "=r"(r[0]), "=r"(r[1]), "=r"(r[2]), "=r"(r[3]) : "r"(addr));
}
__device__ __forceinline__ void ldsm4t(uint32_t* r, uint32_t addr) {
    asm volatile("ldmatrix.sync.aligned.m8n8.x4.trans.shared.b16 {%0,%1,%2,%3}, [%4];"
        : "=r"(r[0]), "=r"(r[1]), "=r"(r[2]), "=r"(r[3]) : "r"(addr));
}
__device__ __forceinline__ void mma16816(float* d, const uint32_t* a, const uint32_t* b) {
    asm volatile(
        "mma.sync.aligned.m16n8k16.row.col.f32.bf16.bf16.f32 "
        "{%0,%1,%2,%3}, {%4,%5,%6,%7}, {%8,%9}, {%0,%1,%2,%3};"
        : "+f"(d[0]), "+f"(d[1]), "+f"(d[2]), "+f"(d[3])
        : "r"(a[0]), "r"(a[1]), "r"(a[2]), "r"(a[3]), "r"(b[0]), "r"(b[1]));
}
__device__ __forceinline__ uint32_t sw128(uint32_t off) {
    return off ^ ((off >> 3) & 0x70);
}
__device__ __forceinline__ void split_bf16(float v, __nv_bfloat16& h, __nv_bfloat16& l) {
    h = __float2bfloat16(v);
    l = __float2bfloat16(v - __bfloat162float(h));
}

// smem: 3 stages x 64KB. Stage: Ah | Al | Bh | Bl (16KB each)
#define STAGE_BYTES 65536
#define OFF_AH 0
#define OFF_AL 16384
#define OFF_BH 32768
#define OFF_BL 49152
#define GEMM_SMEM (3 * STAGE_BYTES)

// ============================================================================
// Generic HMMA GEMM: D[m,n] = alpha * sum_k A[m,k]*B[n,k]  (bf16x3, batched)
// K-major operands. mode 0: fp32 out; mode 1: bf16 hi/lo out.  (R7 config)
// ============================================================================
__global__ void __launch_bounds__(256, 1)
gemm_bf16x3(const __nv_bfloat16* __restrict__ Ah, const __nv_bfloat16* __restrict__ Al,
            const __nv_bfloat16* __restrict__ Bh, const __nv_bfloat16* __restrict__ Bl,
            float* __restrict__ Df, __nv_bfloat16* __restrict__ Dh, __nv_bfloat16* __restrict__ Dl,
            int N, int K,
            long long sA, long long sB, long long sD,
            float alpha, int mode)
{
    extern __shared__ char smem[];
    const int b = blockIdx.z;
    Ah += (long long)b * sA;  Al += (long long)b * sA;
    Bh += (long long)b * sB;  Bl += (long long)b * sB;

    const int m0 = blockIdx.y * 128;
    const int n0 = blockIdx.x * 128;
    const int tid = (int)threadIdx.x;
    const int wid = tid >> 5;
    const int lid = tid & 31;
    const int wm = (wid >> 2) * 64;
    const int wn = (wid & 3) * 32;

    const uint32_t sb = smem_u32(smem);
    const int nch = K >> 6;

    auto load_chunk = [&](int kc, int stage) {
        const long long kofs = (long long)kc * 64;
        const uint32_t sbase = sb + stage * STAGE_BYTES;
#pragma unroll
        for (int j = 0; j < 4; j++) {
            int idx = j * 256 + tid;
            int r   = idx >> 3;
            int cb  = (idx & 7) << 4;
            uint32_t sw = sw128((uint32_t)(r * 128 + cb));
            long long ea = (long long)(m0 + r) * K + kofs + (cb >> 1);
            long long eb = (long long)(n0 + r) * K + kofs + (cb >> 1);
            cp16(sbase + OFF_AH + sw, Ah + ea);
            cp16(sbase + OFF_AL + sw, Al + ea);
            cp16(sbase + OFF_BH + sw, Bh + eb);
            cp16(sbase + OFF_BL + sw, Bl + eb);
        }
        CP_COMMIT();
    };

    float acc[4][4][4];
#pragma unroll
    for (int i = 0; i < 4; i++)
#pragma unroll
        for (int j = 0; j < 4; j++)
#pragma unroll
            for (int c = 0; c < 4; c++) acc[i][j][c] = 0.0f;

    const int a_row = wm + (lid & 15);
    const int a_cb  = (lid >> 4) * 16;
    const int b_row = wn + (lid & 7) + ((lid >> 4) & 1) * 8;
    const int b_cb  = ((lid >> 3) & 1) * 16;

    uint32_t ahf[2][4][4], alf[2][4][4], bhf[2][2][4], blf[2][2][4];

    auto ldfrags = [&](int k16, int buf, uint32_t sbase) {
        const int kb = k16 * 32;
#pragma unroll
        for (int mt = 0; mt < 4; mt++) {
            uint32_t sw = sw128((uint32_t)((a_row + mt * 16) * 128 + kb + a_cb));
            ldsm4(ahf[buf][mt], sbase + OFF_AH + sw);
            ldsm4(alf[buf][mt], sbase + OFF_AL + sw);
        }
#pragma unroll
        for (int np = 0; np < 2; np++) {
            uint32_t sw = sw128((uint32_t)((b_row + np * 16) * 128 + kb + b_cb));
            ldsm4(bhf[buf][np], sbase + OFF_BH + sw);
            ldsm4(blf[buf][np], sbase + OFF_BL + sw);
        }
    };

    load_chunk(0, 0);
    if (nch > 1) load_chunk(1, 1);
    if (nch > 2) load_chunk(2, 2);

    for (int i = 0; i < nch; i++) {
        const int s = i % 3;
        const int rem = nch - 1 - i;
        if (rem >= 2)      { CP_WAIT2(); }
        else if (rem == 1) { CP_WAIT1(); }
        else               { CP_WAIT0(); }
        __syncthreads();

        const uint32_t sbase = sb + s * STAGE_BYTES;
        ldfrags(0, 0, sbase);
        int cur = 0;
#pragma unroll
        for (int k16 = 0; k16 < 4; k16++) {
            if (k16 < 3) ldfrags(k16 + 1, cur ^ 1, sbase);
            if (k16 == 3) {
                __syncthreads();
                if (i + 3 < nch) load_chunk(i + 3, s);
            }
#pragma unroll
            for (int p = 0; p < 3; p++) {
#pragma unroll
                for (int mt = 0; mt < 4; mt++) {
                    const uint32_t* af = (p == 2) ? alf[cur][mt] : ahf[cur][mt];
#pragma unroll
                    for (int nt = 0; nt < 4; nt++) {
                        const uint32_t* bf = (p == 1) ? &blf[cur][nt >> 1][(nt & 1) * 2]
                                                      : &bhf[cur][nt >> 1][(nt & 1) * 2];
                        mma16816(acc[mt][nt], af, bf);
                    }
                }
            }
            cur ^= 1;
        }
    }

    const int er = lid >> 2;
    const int ec = (lid & 3) * 2;
#pragma unroll
    for (int mt = 0; mt < 4; mt++) {
#pragma unroll
        for (int nt = 0; nt < 4; nt++) {
            const long long row0 = m0 + wm + mt * 16 + er;
            const long long col  = n0 + wn + nt * 8 + ec;
            if (mode == 0) {
                float2 v0, v1;
                v0.x = acc[mt][nt][0] * alpha; v0.y = acc[mt][nt][1] * alpha;
                v1.x = acc[mt][nt][2] * alpha; v1.y = acc[mt][nt][3] * alpha;
                *(float2*)(Df + (long long)b * sD + row0 * N + col)       = v0;
                *(float2*)(Df + (long long)b * sD + (row0 + 8) * N + col) = v1;
            } else {
                float p0 = acc[mt][nt][0] * alpha, p1 = acc[mt][nt][1] * alpha;
                float p2 = acc[mt][nt][2] * alpha, p3 = acc[mt][nt][3] * alpha;
                __nv_bfloat16 h0, h1, h2, h3, l0, l1, l2, l3;
                split_bf16(p0, h0, l0); split_bf16(p1, h1, l1);
                split_bf16(p2, h2, l2); split_bf16(p3, h3, l3);
                long long base = (long long)b * sD;
                *(__nv_bfloat162*)(Dh + base + row0 * N + col)       = __nv_bfloat162(h0, h1);
                *(__nv_bfloat162*)(Dh + base + (row0 + 8) * N + col) = __nv_bfloat162(h2, h3);
                *(__nv_bfloat162*)(Dl + base + row0 * N + col)       = __nv_bfloat162(l0, l1);
                *(__nv_bfloat162*)(Dl + base + (row0 + 8) * N + col) = __nv_bfloat162(l2, l3);
            }
        }
    }
}

// ============================================================================
// Trans-trans GEMM: D[m,n] = alpha * sum_k A[k,m]*B[k,n]  (bf16x3, batched)
// A stored [K, ldA] (m contiguous), B stored [K, ldB] (n contiguous).
// ============================================================================
__global__ void __launch_bounds__(256, 1)
gemm_tt_bf16x3(const __nv_bfloat16* __restrict__ Ah, const __nv_bfloat16* __restrict__ Al, int ldA,
               const __nv_bfloat16* __restrict__ Bh, const __nv_bfloat16* __restrict__ Bl, int ldB,
               __nv_bfloat16* __restrict__ Dh, __nv_bfloat16* __restrict__ Dl,
               int N, int K,
               long long sA, long long sB, long long sD,
               float alpha)
{
    extern __shared__ char smem[];
    const int b = blockIdx.z;
    Ah += (long long)b * sA;  Al += (long long)b * sA;
    Bh += (long long)b * sB;  Bl += (long long)b * sB;

    const int m0 = blockIdx.y * 128;
    const int n0 = blockIdx.x * 128;
    const int tid = (int)threadIdx.x;
    const int wid = tid >> 5;
    const int lid = tid & 31;
    const int wm = (wid >> 2) * 64;
    const int wn = (wid & 3) * 32;

    const uint32_t sb = smem_u32(smem);

    auto load_chunk = [&](int kc, int stage) {
        const uint32_t sbase = sb + stage * STAGE_BYTES;
        const long long s0 = (long long)kc * 64;
#pragma unroll
        for (int j = 0; j < 4; j++) {
            int idx = j * 256 + tid;
            int r   = idx >> 4;
            int cb  = (idx & 15) << 4;
            uint32_t sw = (uint32_t)(r * 256 + cb) ^ (uint32_t)((r & 7) << 4);
            cp16(sbase + OFF_AH + sw, Ah + (s0 + r) * ldA + m0 + (cb >> 1));
            cp16(sbase + OFF_AL + sw, Al + (s0 + r) * ldA + m0 + (cb >> 1));
            cp16(sbase + OFF_BH + sw, Bh + (s0 + r) * ldB + n0 + (cb >> 1));
            cp16(sbase + OFF_BL + sw, Bl + (s0 + r) * ldB + n0 + (cb >> 1));
        }
        CP_COMMIT();
    };

    float acc[4][4][4];
#pragma unroll
    for (int i = 0; i < 4; i++)
#pragma unroll
        for (int j = 0; j < 4; j++)
#pragma unroll
            for (int c = 0; c < 4; c++) acc[i][j][c] = 0.0f;

    const int a_krow  = ((lid >> 4) & 1) * 8 + (lid & 7);
    const int a_mbyte = ((lid >> 3) & 1) * 16;
    const int b_krow  = ((lid >> 3) & 1) * 8 + (lid & 7);
    const int b_nbyte = ((lid >> 4) & 1) * 16;

    uint32_t ahf[2][4][4], alf[2][4][4], bhf[2][2][4], blf[2][2][4];

    auto ldfrags = [&](int k16, int buf, uint32_t sbase) {
#pragma unroll
        for (int mt = 0; mt < 4; mt++) {
            uint32_t off = (uint32_t)((k16 * 16 + a_krow) * 256 + (wm + mt * 16) * 2 + a_mbyte);
            off ^= (uint32_t)((a_krow & 7) << 4);
            ldsm4t(ahf[buf][mt], sbase + OFF_AH + off);
            ldsm4t(alf[buf][mt], sbase + OFF_AL + off);
        }
#pragma unroll
        for (int np = 0; np < 2; np++) {
            uint32_t off = (uint32_t)((k16 * 16 + b_krow) * 256 + (wn + np * 16) * 2 + b_nbyte);
            off ^= (uint32_t)((b_krow & 7) << 4);
            ldsm4t(bhf[buf][np], sbase + OFF_BH + off);
            ldsm4t(blf[buf][np], sbase + OFF_BL + off);
        }
    };

    const int nch = K >> 6;
    load_chunk(0, 0);
    if (nch > 1) load_chunk(1, 1);
    if (nch > 2) load_chunk(2, 2);

    for (int i = 0; i < nch; i++) {
        const int s = i % 3;
        const int rem = nch - 1 - i;
        if (rem >= 2)      { CP_WAIT2(); }
        else if (rem == 1) { CP_WAIT1(); }
        else               { CP_WAIT0(); }
        __syncthreads();

        const uint32_t sbase = sb + s * STAGE_BYTES;
        ldfrags(0, 0, sbase);
        int cur = 0;
#pragma unroll
        for (int k16 = 0; k16 < 4; k16++) {
            if (k16 < 3) ldfrags(k16 + 1, cur ^ 1, sbase);
            if (k16 == 3) {
                __syncthreads();
                if (i + 3 < nch) load_chunk(i + 3, s);
            }
#pragma unroll
            for (int p = 0; p < 3; p++) {
#pragma unroll
                for (int mt = 0; mt < 4; mt++) {
                    const uint32_t* af = (p == 2) ? alf[cur][mt] : ahf[cur][mt];
#pragma unroll
                    for (int nt = 0; nt < 4; nt++) {
                        const uint32_t* bf = (p == 1) ? &blf[cur][nt >> 1][(nt & 1) * 2]
                                                      : &bhf[cur][nt >> 1][(nt & 1) * 2];
                        mma16816(acc[mt][nt], af, bf);
                    }
                }
            }
            cur ^= 1;
        }
    }

    const int er = lid >> 2;
    const int ec = (lid & 3) * 2;
    const long long base = (long long)b * sD;
#pragma unroll
    for (int mt = 0; mt < 4; mt++) {
#pragma unroll
        for (int nt = 0; nt < 4; nt++) {
            const long long row0 = m0 + wm + mt * 16 + er;
            const long long col  = n0 + wn + nt * 8 + ec;
            float p0 = acc[mt][nt][0] * alpha, p1 = acc[mt][nt][1] * alpha;
            float p2 = acc[mt][nt][2] * alpha, p3 = acc[mt][nt][3] * alpha;
            __nv_bfloat16 h0, h1, h2, h3, l0, l1, l2, l3;
            split_bf16(p0, h0, l0); split_bf16(p1, h1, l1);
            split_bf16(p2, h2, l2); split_bf16(p3, h3, l3);
            *(__nv_bfloat162*)(Dh + base + row0 * N + col)       = __nv_bfloat162(h0, h1);
            *(__nv_bfloat162*)(Dh + base + (row0 + 8) * N + col) = __nv_bfloat162(h2, h3);
            *(__nv_bfloat162*)(Dl + base + row0 * N + col)       = __nv_bfloat162(l0, l1);
            *(__nv_bfloat162*)(Dl + base + (row0 + 8) * N + col) = __nv_bfloat162(l2, l3);
        }
    }
}

// ---------------- conversion kernels (vectorized: 8 elems/thread) ----------------
__global__ void conv_x_kernel(const float4* __restrict__ x,
                              uint4* __restrict__ xh4, uint4* __restrict__ xl4)
{
    const int i = blockIdx.x * blockDim.x + threadIdx.x;
    float4 a = x[2 * i];
    float4 c = x[2 * i + 1];
    __nv_bfloat16 h[8], l[8];
    split_bf16(a.x, h[0], l[0]); split_bf16(a.y, h[1], l[1]);
    split_bf16(a.z, h[2], l[2]); split_bf16(a.w, h[3], l[3]);
    split_bf16(c.x, h[4], l[4]); split_bf16(c.y, h[5], l[5]);
    split_bf16(c.z, h[6], l[6]); split_bf16(c.w, h[7], l[7]);
    uint4 vh, vl;
    __nv_bfloat162 t0(h[0], h[1]), t1(h[2], h[3]), t2(h[4], h[5]), t3(h[6], h[7]);
    __nv_bfloat162 u0(l[0], l[1]), u1(l[2], l[3]), u2(l[4], l[5]), u3(l[6], l[7]);
    vh.x = *(uint32_t*)&t0; vh.y = *(uint32_t*)&t1; vh.z = *(uint32_t*)&t2; vh.w = *(uint32_t*)&t3;
    vl.x = *(uint32_t*)&u0; vl.y = *(uint32_t*)&u1; vl.z = *(uint32_t*)&u2; vl.w = *(uint32_t*)&u3;
    xh4[i] = vh;
    xl4[i] = vl;
}

// ---------------- launcher (R14 schedule, vectorized weight convs) ----------------
extern "C" void kernel_launch(void* const* d_in, const int* in_sizes, int n_in,
                              void* d_out, int out_size)
{
    const float* x  = (const float*)d_in[0];
    const float* Wt = (const float*)d_in[1];
    const float* Wp = (const float*)d_in[2];
    const float* Wg = (const float*)d_in[3];
    float* out = (float*)d_out;

    __nv_bfloat16 *xh, *xl, *Th, *Tl, *Fh, *Fl, *Ph, *Pl, *Qh, *Ql;
    __nv_bfloat16 *Wth, *Wtl, *Wph, *Wpl, *Wgh, *Wgl;
    cudaGetSymbolAddress((void**)&xh, g_xh);   cudaGetSymbolAddress((void**)&xl, g_xl);
    cudaGetSymbolAddress((void**)&Th, g_Th);   cudaGetSymbolAddress((void**)&Tl, g_Tl);
    cudaGetSymbolAddress((void**)&Fh, g_Fh);   cudaGetSymbolAddress((void**)&Fl, g_Fl);
    cudaGetSymbolAddress((void**)&Ph, g_Ph);   cudaGetSymbolAddress((void**)&Pl, g_Pl);
    cudaGetSymbolAddress((void**)&Qh, g_Qh);   cudaGetSymbolAddress((void**)&Ql, g_Ql);
    cudaGetSymbolAddress((void**)&Wth, g_Wth); cudaGetSymbolAddress((void**)&Wtl, g_Wtl);
    cudaGetSymbolAddress((void**)&Wph, g_Wph); cudaGetSymbolAddress((void**)&Wpl, g_Wpl);
    cudaGetSymbolAddress((void**)&Wgh, g_Wgh); cudaGetSymbolAddress((void**)&Wgl, g_Wgl);

    cudaFuncSetAttribute(gemm_bf16x3,    cudaFuncAttributeMaxDynamicSharedMemorySize, GEMM_SMEM);
    cudaFuncSetAttribute(gemm_tt_bf16x3, cudaFuncAttributeMaxDynamicSharedMemorySize, GEMM_SMEM);

    static cudaStream_t s2 = nullptr;
    static cudaEvent_t evFork = nullptr, evX0 = nullptr, evX1 = nullptr;
    static cudaEvent_t evWp = nullptr, evW = nullptr, evT = nullptr;
    if (!s2) {
        cudaStreamCreateWithFlags(&s2, cudaStreamNonBlocking);
        cudaEventCreateWithFlags(&evFork, cudaEventDisableTiming);
        cudaEventCreateWithFlags(&evX0,   cudaEventDisableTiming);
        cudaEventCreateWithFlags(&evX1,   cudaEventDisableTiming);
        cudaEventCreateWithFlags(&evWp,   cudaEventDisableTiming);
        cudaEventCreateWithFlags(&evW,    cudaEventDisableTiming);
        cudaEventCreateWithFlags(&evT,    cudaEventDisableTiming);
    }

    const float scale = 1.0f / 32.0f;  // 1/sqrt(1024)
    const int nx = BATCH * NSEQ * FDIM;
    const int nxh = nx / 2;            // elements in 4 batches

    const long long sX = (long long)NSEQ * FDIM;
    const long long sT = (long long)NSEQ * LDIM;
    const long long sP = (long long)LDIM * FDIM;
    const long long sQ = (long long)ODIM * LDIM;
    const int HB = BATCH / 2;

    cudaEventRecord(evFork, 0);

    // ---- stream 0: conv x batches 0-3 ----
    conv_x_kernel<<<nxh / 8 / 256, 256>>>((const float4*)x, (uint4*)xh, (uint4*)xl);
    cudaEventRecord(evX0, 0);

    // ---- stream s2: weight convs (vectorized, Wp first), conv x batches 4-7 ----
    cudaStreamWaitEvent(s2, evFork, 0);
    conv_x_kernel<<<(LDIM * FDIM) / 8 / 256, 256, 0, s2>>>(
        (const float4*)Wp, (uint4*)Wph, (uint4*)Wpl);
    cudaEventRecord(evWp, s2);
    conv_x_kernel<<<(LDIM * FDIM) / 8 / 256, 256, 0, s2>>>(
        (const float4*)Wt, (uint4*)Wth, (uint4*)Wtl);
    conv_x_kernel<<<(ODIM * FDIM) / 8 / 256, 256, 0, s2>>>(
        (const float4*)Wg, (uint4*)Wgh, (uint4*)Wgl);
    conv_x_kernel<<<nxh / 8 / 256, 256, 0, s2>>>(
        (const float4*)(x + (long long)HB * sX),
        (uint4*)(xh + (long long)HB * sX), (uint4*)(xl + (long long)HB * sX));
    cudaEventRecord(evX1, s2);
    cudaEventRecord(evW, s2);

    // ---- stream s2: theta (both halves) ----
    cudaStreamWaitEvent(s2, evX0, 0);
    gemm_bf16x3<<<dim3(LDIM / 128, NSEQ / 128, HB), 256, GEMM_SMEM, s2>>>(
        xh, xl, Wth, Wtl, nullptr, Th, Tl, LDIM, FDIM, sX, 0, sT, 1.0f, 1);
    gemm_bf16x3<<<dim3(LDIM / 128, NSEQ / 128, HB), 256, GEMM_SMEM, s2>>>(
        xh + (long long)HB * sX, xl + (long long)HB * sX, Wth, Wtl, nullptr,
        Th + (long long)HB * sT, Tl + (long long)HB * sT, LDIM, FDIM, sX, 0, sT, 1.0f, 1);
    cudaEventRecord(evT, s2);

    // ---- stream 0: phi[0-3] -> phi[4-7] -> P -> QT -> out ----
    cudaStreamWaitEvent(0, evWp, 0);
    gemm_bf16x3<<<dim3(LDIM / 128, NSEQ / 128, HB), 256, GEMM_SMEM>>>(
        xh, xl, Wph, Wpl, nullptr, Fh, Fl, LDIM, FDIM, sX, 0, sT, 1.0f, 1);
    cudaStreamWaitEvent(0, evX1, 0);
    gemm_bf16x3<<<dim3(LDIM / 128, NSEQ / 128, HB), 256, GEMM_SMEM>>>(
        xh + (long long)HB * sX, xl + (long long)HB * sX, Wph, Wpl, nullptr,
        Fh + (long long)HB * sT, Fl + (long long)HB * sT, LDIM, FDIM, sX, 0, sT, 1.0f, 1);

    // P[l,f] = scale * sum_s phi[s,l] * x[s,f] : M=256, N=1024, K=4096 (tt)
    gemm_tt_bf16x3<<<dim3(FDIM / 128, LDIM / 128, BATCH), 256, GEMM_SMEM>>>(
        Fh, Fl, LDIM, xh, xl, FDIM, Ph, Pl, FDIM, NSEQ, sT, sX, sP, scale);

    cudaStreamWaitEvent(0, evW, 0);
    // QT[o,l] = sum_f Wg[o,f] * P[l,f] : M=1024, N=256, K=1024
    gemm_bf16x3<<<dim3(LDIM / 128, ODIM / 128, BATCH), 256, GEMM_SMEM>>>(
        Wgh, Wgl, Ph, Pl, nullptr, Qh, Ql, LDIM, FDIM, 0, sP, sQ, 1.0f, 1);

    // out[s,o] = sum_l theta[s,l] * QT[o,l] : M=4096, N=1024, K=256
    cudaStreamWaitEvent(0, evT, 0);
    gemm_bf16x3<<<dim3(ODIM / 128, NSEQ / 128, BATCH), 256, GEMM_SMEM>>>(
        Th, Tl, Qh, Ql, out, nullptr, nullptr, ODIM, LDIM, sT, sQ, sX, 1.0f, 0);
}